// round 8
// baseline (speedup 1.0000x reference)
#include <cuda_runtime.h>
#include <cstdint>

// InstantNGP: hash-grid encode + MLP 32->64->64->3 via warp-level tf32 mma.sync.
// Round-6: CTA-cooperative M=64 tile, N-split across 4 warps (warp w owns hidden
// cols [16w,16w+16)) -> B-fragment LDS traffic /4 with NO extra accumulators.
// h0 exchanged through SMEM; epilogue via per-warp partials + CTA reduce.

namespace {

constexpr int S_DIM   = 1024;
constexpr int NPTS    = S_DIM * S_DIM;
constexpr int TBL     = 1 << 19;

constexpr int WARPS   = 4;
constexpr int THREADS = WARPS * 32;
constexpr int MT      = 64;               // points per CTA iteration
constexpr int ITERS   = 8;
constexpr int GRID    = NPTS / (MT * ITERS);   // 2048

// dynamic smem: enc 64x32 floats (8KB) + h0 64x64 floats (16KB)
constexpr int ENC_FLOATS = MT * 32;
constexpr int H0_FLOATS  = MT * 64;
constexpr int DYN_SMEM   = (ENC_FLOATS + H0_FLOATS) * 4;   // 24 KB

__device__ __forceinline__ uint32_t tf32_rna(float x) {
    uint32_t r;
    asm("cvt.rna.tf32.f32 %0, %1;" : "=r"(r) : "f"(x));
    return r;
}

// conflict-free swizzles (xor bits 2..4 with row low bits)
__device__ __forceinline__ int eix(int row, int col) {   // enc: stride 32
    return row * 32 + (col ^ ((row & 7) << 2));
}
__device__ __forceinline__ int hix(int row, int col) {   // h0: stride 64
    return row * 64 + (col ^ ((row & 7) << 2));
}

__device__ __forceinline__ void mma8(float* d,
                                     uint32_t a0, uint32_t a1, uint32_t a2, uint32_t a3,
                                     uint32_t b0, uint32_t b1) {
    asm volatile(
        "mma.sync.aligned.m16n8k8.row.col.f32.tf32.tf32.f32 "
        "{%0,%1,%2,%3},{%4,%5,%6,%7},{%8,%9},{%0,%1,%2,%3};"
        : "+f"(d[0]), "+f"(d[1]), "+f"(d[2]), "+f"(d[3])
        : "r"(a0), "r"(a1), "r"(a2), "r"(a3), "r"(b0), "r"(b1));
}

__global__ __launch_bounds__(THREADS, 4) void ngp_mma_kernel(
    const float2* __restrict__ xy,
    const float2* __restrict__ tab,
    const float*  __restrict__ W0,     // (32, 64) [k][n]
    const float*  __restrict__ W1,     // (64, 64) [k][n]
    const float*  __restrict__ W2,     // (64, 3)
    float*        __restrict__ out)    // (3, S, S)
{
    __shared__ uint2 w0f[4 * 8 * 32];   //  8 KB  B frags layer0
    __shared__ uint2 w1f[8 * 8 * 32];   // 16 KB  B frags layer1
    __shared__ float w2s[3 * 64];       // packed [j][c]
    extern __shared__ uint32_t dynscr[];
    uint32_t* enc = dynscr;                       // 64 x 32 (swizzled)
    uint32_t* h0  = dynscr + ENC_FLOATS;          // 64 x 64 (swizzled)
    float*    part = reinterpret_cast<float*>(dynscr);  // aliases enc (64*12 floats)

    const int tid = threadIdx.x;

    // ---- stage weights in fragment order (once per CTA) ----
    for (int i = tid; i < 4 * 8 * 32; i += THREADS) {
        const int k = i >> 8, nt = (i >> 5) & 7, ln = i & 31;
        const int t = ln & 3, g = ln >> 2;
        w0f[i] = make_uint2(tf32_rna(W0[(8 * k + t) * 64 + nt * 8 + g]),
                            tf32_rna(W0[(8 * k + t + 4) * 64 + nt * 8 + g]));
    }
    for (int i = tid; i < 8 * 8 * 32; i += THREADS) {
        const int k = i >> 8, nt = (i >> 5) & 7, ln = i & 31;
        const int t = ln & 3, g = ln >> 2;
        w1f[i] = make_uint2(tf32_rna(W1[(8 * k + t) * 64 + nt * 8 + g]),
                            tf32_rna(W1[(8 * k + t + 4) * 64 + nt * 8 + g]));
    }
    for (int i = tid; i < 3 * 64; i += THREADS) {
        const int j = i >> 6, c = i & 63;
        w2s[i] = W2[c * 3 + j];
    }

    const int wid  = tid >> 5;
    const int lane = tid & 31;
    const int t    = lane & 3;          // threadIDInGroup
    const int g    = lane >> 2;         // groupID
    const int h    = tid & 1;           // level parity for encode
    const int pt   = tid >> 1;          // point (0..63) for encode

    // floor(16 * 1.5^l): even levels / odd levels
    const int res_e[8] = {16, 36, 81, 182, 410, 922, 2075, 4670};
    const int res_o[8] = {24, 54, 121, 273, 615, 1383, 3113, 7006};

    for (int it = 0; it < ITERS; it++) {
        const int base = (blockIdx.x * ITERS + it) * MT;
        __syncthreads();   // scratch reuse guard (enc/part, h0)

        // ---- encode: 64 points, 2 threads/point (even/odd levels) ----
        {
            const float2 p = __ldg(&xy[base + pt]);
            const float c0 = p.x, c1 = p.y;
#pragma unroll
            for (int lp = 0; lp < 8; lp++) {
                const int res   = h ? res_o[lp] : res_e[lp];
                const int level = 2 * lp + h;
                const bool dense = (lp < 5);

                const float fres = (float)res;
                const float px = c0 * fres;
                const float py = c1 * fres;
                const float fx = floorf(px);
                const float fy = floorf(py);
                const float wx = px - fx;
                const float wy = py - fy;
                const int ix = (int)fx;
                const int iy = (int)fy;

                int i00, i01, i10, i11;
                if (dense) {
                    const int r1 = res + 1;
                    i00 = ix + iy * r1;
                    i01 = i00 + r1;
                    i10 = i00 + 1;
                    i11 = i01 + 1;
                } else {
                    const uint32_t P = 2654435761u;
                    const uint32_t ux = (uint32_t)ix;
                    const uint32_t uy = (uint32_t)iy;
                    const uint32_t hy0 = uy * P;
                    const uint32_t hy1 = (uy + 1u) * P;
                    i00 = (int)((ux        ^ hy0) & (uint32_t)(TBL - 1));
                    i01 = (int)((ux        ^ hy1) & (uint32_t)(TBL - 1));
                    i10 = (int)(((ux + 1u) ^ hy0) & (uint32_t)(TBL - 1));
                    i11 = (int)(((ux + 1u) ^ hy1) & (uint32_t)(TBL - 1));
                }

                const float2* lt = tab + (size_t)level * TBL;
                const float2 a00 = __ldg(lt + i00);
                const float2 a01 = __ldg(lt + i01);
                const float2 a10 = __ldg(lt + i10);
                const float2 a11 = __ldg(lt + i11);

                const float w00 = (1.0f - wx) * (1.0f - wy);
                const float w01 = (1.0f - wx) * wy;
                const float w10 = wx * (1.0f - wy);
                const float w11 = wx * wy;

                const float f0 = a00.x * w00 + a01.x * w01 + a10.x * w10 + a11.x * w11;
                const float f1 = a00.y * w00 + a01.y * w01 + a10.y * w10 + a11.y * w11;

                *reinterpret_cast<uint2*>(&enc[eix(pt, 4 * lp + 2 * h)]) =
                    make_uint2(tf32_rna(f0), tf32_rna(f1));
            }
        }
        __syncthreads();

        // ---- layer 0: warp w computes cols [16w,16w+16) for all 64 rows ----
        float C[4][2][4];
#pragma unroll
        for (int m = 0; m < 4; m++)
#pragma unroll
            for (int j = 0; j < 2; j++)
#pragma unroll
                for (int q = 0; q < 4; q++) C[m][j][q] = 0.0f;

#pragma unroll
        for (int k = 0; k < 4; k++) {
            uint32_t a[4][4];
#pragma unroll
            for (int m = 0; m < 4; m++) {
                const int r0 = 16 * m + g, r1 = r0 + 8;
                a[m][0] = enc[eix(r0, 8 * k + t)];
                a[m][1] = enc[eix(r1, 8 * k + t)];
                a[m][2] = enc[eix(r0, 8 * k + t + 4)];
                a[m][3] = enc[eix(r1, 8 * k + t + 4)];
            }
#pragma unroll
            for (int j = 0; j < 2; j++) {
                const uint2 b = w0f[(k * 8 + 2 * wid + j) * 32 + lane];
#pragma unroll
                for (int m = 0; m < 4; m++)
                    mma8(C[m][j], a[m][0], a[m][1], a[m][2], a[m][3], b.x, b.y);
            }
        }

        // ---- relu + store h0 slice ----
#pragma unroll
        for (int m = 0; m < 4; m++) {
            const int r0 = 16 * m + g, r1 = r0 + 8;
#pragma unroll
            for (int j = 0; j < 2; j++) {
                const int col = (2 * wid + j) * 8 + 2 * t;
                *reinterpret_cast<uint2*>(&h0[hix(r0, col)]) =
                    make_uint2(tf32_rna(fmaxf(C[m][j][0], 0.0f)),
                               tf32_rna(fmaxf(C[m][j][1], 0.0f)));
                *reinterpret_cast<uint2*>(&h0[hix(r1, col)]) =
                    make_uint2(tf32_rna(fmaxf(C[m][j][2], 0.0f)),
                               tf32_rna(fmaxf(C[m][j][3], 0.0f)));
            }
        }
        __syncthreads();

        // ---- layer 1: warp w computes cols [16w,16w+16) ----
#pragma unroll
        for (int m = 0; m < 4; m++)
#pragma unroll
            for (int j = 0; j < 2; j++)
#pragma unroll
                for (int q = 0; q < 4; q++) C[m][j][q] = 0.0f;

#pragma unroll
        for (int k = 0; k < 8; k++) {
            uint32_t a[4][4];
#pragma unroll
            for (int m = 0; m < 4; m++) {
                const int r0 = 16 * m + g, r1 = r0 + 8;
                a[m][0] = h0[hix(r0, 8 * k + t)];
                a[m][1] = h0[hix(r1, 8 * k + t)];
                a[m][2] = h0[hix(r0, 8 * k + t + 4)];
                a[m][3] = h0[hix(r1, 8 * k + t + 4)];
            }
#pragma unroll
            for (int j = 0; j < 2; j++) {
                const uint2 b = w1f[(k * 8 + 2 * wid + j) * 32 + lane];
#pragma unroll
                for (int m = 0; m < 4; m++)
                    mma8(C[m][j], a[m][0], a[m][1], a[m][2], a[m][3], b.x, b.y);
            }
        }

        // ---- epilogue: warp-partial 16-col dot with W2, then CTA reduce ----
        float pa[4][2][3];
#pragma unroll
        for (int m = 0; m < 4; m++)
#pragma unroll
            for (int r = 0; r < 2; r++)
#pragma unroll
                for (int j = 0; j < 3; j++) pa[m][r][j] = 0.0f;

#pragma unroll
        for (int j01 = 0; j01 < 2; j01++) {
            const int cA = (2 * wid + j01) * 8 + 2 * t;
            float2 w[3];
#pragma unroll
            for (int j = 0; j < 3; j++)
                w[j] = *reinterpret_cast<const float2*>(&w2s[j * 64 + cA]);
#pragma unroll
            for (int m = 0; m < 4; m++) {
                const float vA0 = fmaxf(C[m][j01][0], 0.0f);
                const float vB0 = fmaxf(C[m][j01][1], 0.0f);
                const float vA1 = fmaxf(C[m][j01][2], 0.0f);
                const float vB1 = fmaxf(C[m][j01][3], 0.0f);
#pragma unroll
                for (int j = 0; j < 3; j++) {
                    pa[m][0][j] += vA0 * w[j].x + vB0 * w[j].y;
                    pa[m][1][j] += vA1 * w[j].x + vB1 * w[j].y;
                }
            }
        }
#pragma unroll
        for (int m = 0; m < 4; m++)
#pragma unroll
            for (int r = 0; r < 2; r++)
#pragma unroll
                for (int j = 0; j < 3; j++) {
                    float v = pa[m][r][j];
                    v += __shfl_xor_sync(0xffffffffu, v, 1);
                    v += __shfl_xor_sync(0xffffffffu, v, 2);
                    pa[m][r][j] = v;
                }
        __syncthreads();   // enc reads done (layer0); part aliases enc
        if (t == 0) {
#pragma unroll
            for (int m = 0; m < 4; m++)
#pragma unroll
                for (int r = 0; r < 2; r++) {
                    const int row = 16 * m + g + 8 * r;
#pragma unroll
                    for (int j = 0; j < 3; j++)
                        part[row * 12 + wid * 3 + j] = pa[m][r][j];
                }
        }
        __syncthreads();

        for (int i = tid; i < 3 * MT; i += THREADS) {
            const int j = i >> 6, p = i & 63;
            const float s = part[p * 12 + 0 + j] + part[p * 12 + 3 + j] +
                            part[p * 12 + 6 + j] + part[p * 12 + 9 + j];
            out[j * NPTS + base + p] = s;
        }
    }
}

}  // namespace

extern "C" void kernel_launch(void* const* d_in, const int* in_sizes, int n_in,
                              void* d_out, int out_size) {
    (void)in_sizes; (void)n_in; (void)out_size;
    const float2* xy  = (const float2*)d_in[0];
    const float2* tab = (const float2*)d_in[1];
    const float*  W0  = (const float*)d_in[2];
    const float*  W1  = (const float*)d_in[3];
    const float*  W2  = (const float*)d_in[4];
    float* out = (float*)d_out;

    cudaFuncSetAttribute(ngp_mma_kernel,
                         cudaFuncAttributeMaxDynamicSharedMemorySize, DYN_SMEM);
    ngp_mma_kernel<<<GRID, THREADS, DYN_SMEM>>>(xy, tab, W0, W1, W2, out);
}